// round 15
// baseline (speedup 1.0000x reference)
#include <cuda_runtime.h>
#include <cuda_fp16.h>
#include <math.h>
#include <stdint.h>

#define QLEN 1024
#define KLEN 2048
#define RLEN 2048
#define BSZ  2
#define DM   1024
#define NH   16
#define DH   64
#define NHD  1024   // NH*DH

#define BDSTRIDE 2049
#define BDSZ     2098176   // per-(b,n) shifted-BD buffer

// scale folded with log2(e): exp(0.125*x) = exp2(SCL*x)
#define SCL 0.18033688f

// -------------------- scratch (device globals) ------------------------------
__device__ __half g_qh16[QLEN * BSZ * NHD];
__device__ __half g_kvh[KLEN * BSZ * 2 * NHD];
__device__ __half g_rk16[RLEN * NHD];
__device__ __half g_bd[(size_t)BSZ * NH * BDSZ];   // fp16, pre-scaled by SCL
__device__ __half g_avh[QLEN * BSZ * NHD];
__device__ __half g_w16[KLEN * BSZ * DM];
__device__ __half g_r16[RLEN * DM];
__device__ __half g_wq16[DM * NHD];
__device__ __half g_wkv16[DM * 2 * NHD];
__device__ __half g_wr16[DM * NHD];
__device__ __half g_wo16[NHD * DM];

// -------------------- helpers ------------------------------------------------
__device__ __forceinline__ uint32_t h2(float x, float y) {
    __half2 h = __floats2half2_rn(x, y);
    return *reinterpret_cast<uint32_t*>(&h);
}

__device__ __forceinline__ float ex2f(float x) {
    float y; asm("ex2.approx.f32 %0, %1;" : "=f"(y) : "f"(x)); return y;
}

__device__ __forceinline__ void mma16(float* d, const uint32_t* a, uint32_t b0, uint32_t b1) {
    asm volatile(
        "mma.sync.aligned.m16n8k16.row.col.f32.f16.f16.f32 "
        "{%0,%1,%2,%3},{%4,%5,%6,%7},{%8,%9},{%0,%1,%2,%3};\n"
        : "+f"(d[0]), "+f"(d[1]), "+f"(d[2]), "+f"(d[3])
        : "r"(a[0]), "r"(a[1]), "r"(a[2]), "r"(a[3]), "r"(b0), "r"(b1));
}

__device__ __forceinline__ void cpa16(uint32_t dst, const void* src) {
    asm volatile("cp.async.ca.shared.global [%0], [%1], 16;" :: "r"(dst), "l"(src));
}
__device__ __forceinline__ void cpa_commit() {
    asm volatile("cp.async.commit_group;");
}
template<int N> __device__ __forceinline__ void cpa_wait() {
    asm volatile("cp.async.wait_group %0;" :: "n"(N));
}

__device__ __forceinline__ void ldmx4t(uint32_t& r0, uint32_t& r1, uint32_t& r2, uint32_t& r3,
                                       uint32_t addr) {
    asm volatile("ldmatrix.sync.aligned.m8n8.x4.trans.shared.b16 {%0,%1,%2,%3}, [%4];"
                 : "=r"(r0), "=r"(r1), "=r"(r2), "=r"(r3) : "r"(addr));
}
__device__ __forceinline__ void ldmx4(uint32_t& r0, uint32_t& r1, uint32_t& r2, uint32_t& r3,
                                      uint32_t addr) {
    asm volatile("ldmatrix.sync.aligned.m8n8.x4.shared.b16 {%0,%1,%2,%3}, [%4];"
                 : "=r"(r0), "=r"(r1), "=r"(r2), "=r"(r3) : "r"(addr));
}

__device__ __forceinline__ void store_pair(float* p, float a, float b) {
    *(float2*)p = make_float2(a, b);
}
__device__ __forceinline__ void store_pair(__half* p, float a, float b) {
    *(__half2*)p = __floats2half2_rn(a, b);
}

// -------------------- fp32 -> fp16 convert ----------------------------------
__global__ void f2h_kernel(const float* __restrict__ in, __half* __restrict__ out, int n4) {
    int i = blockIdx.x * blockDim.x + threadIdx.x;
    if (i < n4) {
        float4 v = ((const float4*)in)[i];
        ((__half2*)out)[i * 2]     = __floats2half2_rn(v.x, v.y);
        ((__half2*)out)[i * 2 + 1] = __floats2half2_rn(v.z, v.w);
    }
}

// -------------------- fp16 GEMM (validated R13) ------------------------------
#define GS 3
#define AH (128 * 40)
#define BH (32 * 136)
#define STH (AH + BH)
template <typename OutT>
__global__ __launch_bounds__(256) void gemm_fp16(
    const __half* __restrict__ A, const __half* __restrict__ B,
    OutT* __restrict__ C, int M, int N, int K)
{
    __shared__ __half Sg[GS * STH];
    const uint32_t sbase = (uint32_t)__cvta_generic_to_shared(Sg);

    const int tid  = threadIdx.x;
    const int lane = tid & 31;
    const int warp = tid >> 5;
    const int row = lane >> 2;
    const int qd  = lane & 3;
    const int wm = (warp >> 2) * 64;
    const int wn = (warp & 3) * 32;
    const int row0 = blockIdx.y * 128, col0 = blockIdx.x * 128;

    float acc[4][4][4];
    #pragma unroll
    for (int i = 0; i < 4; i++)
        #pragma unroll
        for (int j = 0; j < 4; j++)
            #pragma unroll
            for (int r = 0; r < 4; r++) acc[i][j][r] = 0.0f;

    const int am = tid >> 1, ah = (tid & 1) * 16;
    const int bk = tid >> 3, bh = (tid & 7) * 16;
    const __half* aptr = A + (size_t)(row0 + am) * K + ah;
    const __half* bptr = B + (size_t)bk * N + col0 + bh;

    const int nsteps = K >> 5;
    const int a_r = ((lane >> 3) & 1) * 8 + (lane & 7);
    const int a_c = ((lane >> 4) & 1) * 8;

    #pragma unroll
    for (int s = 0; s < GS; s++) {
        if (s < nsteps) {
            uint32_t ab = sbase + (uint32_t)(s * STH + am * 40 + ah) * 2;
            cpa16(ab,      aptr + (s << 5));
            cpa16(ab + 16, aptr + (s << 5) + 8);
            uint32_t bb = sbase + (uint32_t)(s * STH + AH + bk * 136 + bh) * 2;
            cpa16(bb,      bptr + (size_t)(s << 5) * N);
            cpa16(bb + 16, bptr + (size_t)(s << 5) * N + 8);
        }
        cpa_commit();
    }

    int buf = 0;
    for (int t = 0; t < nsteps; t++) {
        cpa_wait<GS - 1>();
        __syncthreads();

        const uint32_t aoff = (uint32_t)(buf * STH);
        const uint32_t boff = (uint32_t)(buf * STH + AH);

        #pragma unroll
        for (int kk = 0; kk < 32; kk += 16) {
            uint32_t af[4][4];
            #pragma unroll
            for (int mt = 0; mt < 4; mt++) {
                uint32_t addr = sbase +
                    (aoff + (uint32_t)(wm + mt * 16 + a_r) * 40 + kk + a_c) * 2;
                ldmx4(af[mt][0], af[mt][1], af[mt][2], af[mt][3], addr);
            }
            #pragma unroll
            for (int ns = 0; ns < 2; ns++) {
                uint32_t r0, r1, r2, r3;
                uint32_t addr = sbase +
                    (boff + (kk + (lane & 15)) * 136 + wn + ns * 16 + (lane >> 4) * 8) * 2;
                ldmx4t(r0, r1, r2, r3, addr);
                #pragma unroll
                for (int mt = 0; mt < 4; mt++) {
                    mma16(acc[mt][ns * 2],     af[mt], r0, r1);
                    mma16(acc[mt][ns * 2 + 1], af[mt], r2, r3);
                }
            }
        }
        __syncthreads();

        const int tn = t + GS;
        if (tn < nsteps) {
            uint32_t ab = sbase + (uint32_t)(buf * STH + am * 40 + ah) * 2;
            cpa16(ab,      aptr + (tn << 5));
            cpa16(ab + 16, aptr + (tn << 5) + 8);
            uint32_t bb = sbase + (uint32_t)(buf * STH + AH + bk * 136 + bh) * 2;
            cpa16(bb,      bptr + (size_t)(tn << 5) * N);
            cpa16(bb + 16, bptr + (size_t)(tn << 5) * N + 8);
        }
        cpa_commit();
        buf = (buf + 1 == GS) ? 0 : buf + 1;
    }

    #pragma unroll
    for (int mt = 0; mt < 4; mt++)
        #pragma unroll
        for (int nt = 0; nt < 4; nt++) {
            int r = row0 + wm + mt * 16 + row;
            int c = col0 + wn + nt * 8 + 2 * qd;
            store_pair(&C[(size_t)r * N + c],       acc[mt][nt][0], acc[mt][nt][1]);
            store_pair(&C[(size_t)(r + 8) * N + c], acc[mt][nt][2], acc[mt][nt][3]);
        }
}

// -------------------- BD scores (fp16) -> shifted layout, SCL pre-scale -----
extern __shared__ uint32_t s_dyn[];
__global__ __launch_bounds__(256) void scores_bd_fp16(
    const __half* __restrict__ qh, const __half* __restrict__ rk,
    const float* __restrict__ bias, __half* __restrict__ out)
{
    __half (*Qs)[72] = (__half(*)[72])s_dyn;
    __half (*Ks)[72] = (__half(*)[72])(s_dyn + 128 * 36);

    const int bn = blockIdx.z;
    const int b = bn >> 4, n = bn & 15;
    const int j0 = blockIdx.x * 128, i0 = blockIdx.y * 128;
    const int tid  = threadIdx.x;
    const int lane = tid & 31;
    const int warp = tid >> 5;
    const int row = lane >> 2;
    const int qd  = lane & 3;
    const int wm = (warp >> 2) * 64;
    const int wn = (warp & 3) * 32;

    const int m = tid >> 1, half = (tid & 1) * 32;
    const __half* qrow = qh + (size_t)((i0 + m) * 2 + b) * NHD + n * DH + half;
    const __half* krow = rk + (size_t)(j0 + m) * NHD + n * DH + half;
    const float4* bias4 = (const float4*)(bias + n * DH + half);

    #pragma unroll
    for (int q = 0; q < 4; q++) {
        uint4 v = ((const uint4*)qrow)[q];
        float4 b0 = bias4[2 * q], b1 = bias4[2 * q + 1];
        float2 f0 = __half22float2(*reinterpret_cast<__half2*>(&v.x));
        float2 f1 = __half22float2(*reinterpret_cast<__half2*>(&v.y));
        float2 f2 = __half22float2(*reinterpret_cast<__half2*>(&v.z));
        float2 f3 = __half22float2(*reinterpret_cast<__half2*>(&v.w));
        int d = half + q * 8;
        *(uint2*)&Qs[m][d]     = make_uint2(h2(f0.x + b0.x, f0.y + b0.y),
                                            h2(f1.x + b0.z, f1.y + b0.w));
        *(uint2*)&Qs[m][d + 4] = make_uint2(h2(f2.x + b1.x, f2.y + b1.y),
                                            h2(f3.x + b1.z, f3.y + b1.w));
        *(uint4*)&Ks[m][d] = ((const uint4*)krow)[q];
    }
    __syncthreads();

    float acc[4][4][4];
    #pragma unroll
    for (int i = 0; i < 4; i++)
        #pragma unroll
        for (int j = 0; j < 4; j++)
            #pragma unroll
            for (int r = 0; r < 4; r++) acc[i][j][r] = 0.0f;

    #pragma unroll
    for (int g = 0; g < 4; g++) {
        uint32_t af[4][4];
        #pragma unroll
        for (int mt = 0; mt < 4; mt++) {
            int r = wm + mt * 16 + row;
            const __half* p0 = &Qs[r][g * 16 + 2 * qd];
            af[mt][0] = *(const uint32_t*)p0;
            af[mt][1] = *(const uint32_t*)(p0 + 8 * 72);
            af[mt][2] = *(const uint32_t*)(p0 + 8);
            af[mt][3] = *(const uint32_t*)(p0 + 8 * 72 + 8);
        }
        #pragma unroll
        for (int nt = 0; nt < 4; nt++) {
            int j = wn + nt * 8 + row;
            const __half* pk = &Ks[j][g * 16 + 2 * qd];
            uint32_t b0 = *(const uint32_t*)pk;
            uint32_t b1 = *(const uint32_t*)(pk + 8);
            #pragma unroll
            for (int mt = 0; mt < 4; mt++) mma16(acc[mt][nt], af[mt], b0, b1);
        }
    }

    __syncthreads();
    float (*St)[129] = (float(*)[129])s_dyn;
    #pragma unroll
    for (int mt = 0; mt < 4; mt++)
        #pragma unroll
        for (int nt = 0; nt < 4; nt++) {
            int r = wm + mt * 16 + row;
            int c = wn + nt * 8 + 2 * qd;
            St[r][c]     = acc[mt][nt][0] * SCL;
            St[r][c + 1] = acc[mt][nt][1] * SCL;
            St[r + 8][c]     = acc[mt][nt][2] * SCL;
            St[r + 8][c + 1] = acc[mt][nt][3] * SCL;
        }
    __syncthreads();

    __half* ob = out + (size_t)bn * BDSZ;
    #pragma unroll
    for (int rr = 0; rr < 16; rr++) {
        int r = warp * 16 + rr;
        size_t base = (size_t)(i0 + r) * BDSTRIDE + j0 + 1;
        #pragma unroll
        for (int mth = 0; mth < 4; mth++)
            ob[base + lane + 32 * mth] = __float2half_rn(St[r][lane + 32 * mth]);
    }
}

// zero the "dropped column" positions of the shifted buffer
__global__ void zero_diag(__half* __restrict__ buf) {
    int k = blockIdx.x * blockDim.x + threadIdx.x;
    int bn = k >> 10, kk = k & 1023;
    if (kk >= 1)
        buf[(size_t)bn * BDSZ + (size_t)kk * BDSTRIDE] = __float2half(0.0f);
}

// -------------------- fused attention v6: K & V double-buffered --------------
// 4 SMEM slots (K0,K1,V0,V1), 4 cp.async groups in flight, wait<2> per tile,
// 2 barriers per tile, no mid-tile V wait. Prefetch distance = 2 tiles.
#define KHALF  (128 * 72)
__global__ __launch_bounds__(256, 2) void attn_fused(
    const __half* __restrict__ qh, const __half* __restrict__ kvh,
    const __half* __restrict__ bdbuf, const float* __restrict__ rwb,
    __half* __restrict__ av)
{
    extern __shared__ __half smh[];
    const uint32_t sbase = (uint32_t)__cvta_generic_to_shared(smh);

    const int bn = blockIdx.y;
    const int b = bn >> 4, n = bn & 15;
    const int i0 = blockIdx.x * 128;
    const int tid  = threadIdx.x;
    const int lane = tid & 31;
    const int warp = tid >> 5;
    const int row = lane >> 2;
    const int qd  = lane & 3;
    const int irow = i0 + warp * 16 + row;

    const int st_row = tid >> 1;
    const int st_h   = (tid & 1) * 32;

    const int k_r = ((lane >> 4) & 1) * 8 + (lane & 7);
    const int k_c = ((lane >> 3) & 1) * 8;

    uint32_t qf[4][4];
    {
        const __half* q0 = qh + (size_t)(irow * 2 + b) * NHD + n * DH;
        const __half* q1 = q0 + 16 * NHD;
        const float* bias = rwb + n * DH;
        #pragma unroll
        for (int g = 0; g < 4; g++) {
            int d0 = g * 16 + 2 * qd;
            float2 a0 = __half22float2(*(const __half2*)&q0[d0]);
            float2 a1 = __half22float2(*(const __half2*)&q1[d0]);
            float2 a2 = __half22float2(*(const __half2*)&q0[d0 + 8]);
            float2 a3 = __half22float2(*(const __half2*)&q1[d0 + 8]);
            qf[g][0] = h2((a0.x + bias[d0])   * SCL, (a0.y + bias[d0+1]) * SCL);
            qf[g][1] = h2((a1.x + bias[d0])   * SCL, (a1.y + bias[d0+1]) * SCL);
            qf[g][2] = h2((a2.x + bias[d0+8]) * SCL, (a2.y + bias[d0+9]) * SCL);
            qf[g][3] = h2((a3.x + bias[d0+8]) * SCL, (a3.y + bias[d0+9]) * SCL);
        }
    }

    float Ov[8][4];
    #pragma unroll
    for (int dt = 0; dt < 8; dt++)
        #pragma unroll
        for (int r = 0; r < 4; r++) Ov[dt][r] = 0.0f;
    float l0 = 0.0f, l1 = 0.0f;

    const __half* bdp = bdbuf + (size_t)bn * BDSZ + 1024;

    // staging helpers: slot s in {0,1}=K bufs, {2,3}=V bufs
    // prologue: K0 | V0 | K1 | V1 as 4 groups
    {
        const __half* base0 = kvh + ((size_t)st_row * 2 + b) * (2 * NHD) + n * DH + st_h;
        const __half* base1 = kvh + ((size_t)(128 + st_row) * 2 + b) * (2 * NHD) + n * DH + st_h;
        #pragma unroll
        for (int i = 0; i < 4; i++)
            cpa16(sbase + (uint32_t)(0 * KHALF + st_row * 72 + st_h + i * 8) * 2, base0 + i * 8);
        cpa_commit();
        #pragma unroll
        for (int i = 0; i < 4; i++)
            cpa16(sbase + (uint32_t)(2 * KHALF + st_row * 72 + st_h + i * 8) * 2, base0 + NHD + i * 8);
        cpa_commit();
        #pragma unroll
        for (int i = 0; i < 4; i++)
            cpa16(sbase + (uint32_t)(1 * KHALF + st_row * 72 + st_h + i * 8) * 2, base1 + i * 8);
        cpa_commit();
        #pragma unroll
        for (int i = 0; i < 4; i++)
            cpa16(sbase + (uint32_t)(3 * KHALF + st_row * 72 + st_h + i * 8) * 2, base1 + NHD + i * 8);
        cpa_commit();
    }

    for (int t = 0; t < 16; t++) {
        const int j0 = t * 128;
        const int kb = t & 1;
        const uint32_t koff = (uint32_t)(kb * KHALF);
        const uint32_t voff = (uint32_t)((2 + kb) * KHALF);

        cpa_wait<2>();       // K[t], V[t] resident (K[t+1],V[t+1] may be pending)
        __syncthreads();

        #pragma unroll
        for (int ch = 0; ch < 2; ch++) {
            const int jl = ch * 64;

            // init s with SCL-pre-scaled fp16 shifted-BD
            float s[8][4];
            #pragma unroll
            for (int nt = 0; nt < 8; nt++) {
                int jc = j0 + jl + nt * 8 + 2 * qd;
                uint32_t u0 = __ldcs((const uint32_t*)(bdp + (size_t)irow * KLEN + jc));
                uint32_t u1 = __ldcs((const uint32_t*)(bdp + (size_t)(irow + 8) * KLEN + jc));
                float2 f0 = __half22float2(*reinterpret_cast<__half2*>(&u0));
                float2 f1 = __half22float2(*reinterpret_cast<__half2*>(&u1));
                s[nt][0] = f0.x; s[nt][1] = f0.y;
                s[nt][2] = f1.x; s[nt][3] = f1.y;
            }

            // S += Q~ . K^T
            #pragma unroll
            for (int g = 0; g < 4; g++) {
                #pragma unroll
                for (int ntp = 0; ntp < 4; ntp++) {
                    int j = jl + ntp * 16 + k_r;
                    uint32_t addr = sbase + (koff + (uint32_t)(j * 72 + g * 16 + k_c)) * 2;
                    uint32_t r0, r1, r2, r3;
                    ldmx4(r0, r1, r2, r3, addr);
                    mma16(s[2 * ntp],     qf[g], r0, r1);
                    mma16(s[2 * ntp + 1], qf[g], r2, r3);
                }
            }

            // P = exp2(s); accumulate row sums
            {
                float ps0 = 0.0f, ps1 = 0.0f;
                #pragma unroll
                for (int nt = 0; nt < 8; nt++) {
                    s[nt][0] = ex2f(s[nt][0]);
                    s[nt][1] = ex2f(s[nt][1]);
                    s[nt][2] = ex2f(s[nt][2]);
                    s[nt][3] = ex2f(s[nt][3]);
                    ps0 += s[nt][0] + s[nt][1];
                    ps1 += s[nt][2] + s[nt][3];
                }
                l0 += ps0;
                l1 += ps1;
            }

            // O += P . V
            #pragma unroll
            for (int g = 0; g < 4; g++) {
                uint32_t a[4];
                a[0] = h2(s[2*g][0],   s[2*g][1]);
                a[1] = h2(s[2*g][2],   s[2*g][3]);
                a[2] = h2(s[2*g+1][0], s[2*g+1][1]);
                a[3] = h2(s[2*g+1][2], s[2*g+1][3]);
                #pragma unroll
                for (int dp = 0; dp < 4; dp++) {
                    int jrow = jl + g * 16 + (lane & 15);
                    int dcol = (dp * 2 + (lane >> 4)) * 8;
                    uint32_t addr = sbase + (voff + (uint32_t)(jrow * 72 + dcol)) * 2;
                    uint32_t r0, r1, r2, r3;
                    ldmx4t(r0, r1, r2, r3, addr);
                    mma16(Ov[dp * 2],     a, r0, r1);
                    mma16(Ov[dp * 2 + 1], a, r2, r3);
                }
            }
        }

        __syncthreads();     // slots kb / 2+kb now free for tile t+2

        // issue K[t+2], V[t+2] into the just-freed slots (always commit)
        if (t + 2 < 16) {
            const __half* base2 = kvh + ((size_t)(j0 + 256 + st_row) * 2 + b) * (2 * NHD) + n * DH + st_h;
            #pragma unroll
            for (int i = 0; i < 4; i++)
                cpa16(sbase + (koff + (uint32_t)(st_row * 72 + st_h + i * 8)) * 2, base2 + i * 8);
            cpa_commit();
            #pragma unroll
            for (int i = 0; i < 4; i++)
                cpa16(sbase + (voff + (uint32_t)(st_row * 72 + st_h + i * 8)) * 2, base2 + NHD + i * 8);
            cpa_commit();
        } else {
            cpa_commit();
            cpa_commit();
        }
    }

    cpa_wait<0>();

    {
        float ll0 = l0, ll1 = l1;
        ll0 += __shfl_xor_sync(0xffffffffu, ll0, 1);
        ll0 += __shfl_xor_sync(0xffffffffu, ll0, 2);
        ll1 += __shfl_xor_sync(0xffffffffu, ll1, 1);
        ll1 += __shfl_xor_sync(0xffffffffu, ll1, 2);
        float inv0 = 1.0f / ll0, inv1 = 1.0f / ll1;
        #pragma unroll
        for (int dt = 0; dt < 8; dt++) {
            int d = n * DH + dt * 8 + 2 * qd;
            *(__half2*)&av[(size_t)(irow * 2 + b) * NHD + d] =
                __floats2half2_rn(Ov[dt][0] * inv0, Ov[dt][1] * inv0);
            *(__half2*)&av[(size_t)((irow + 8) * 2 + b) * NHD + d] =
                __floats2half2_rn(Ov[dt][2] * inv1, Ov[dt][3] * inv1);
        }
    }
}

// ---------------------------------------------------------------------------
extern "C" void kernel_launch(void* const* d_in, const int* in_sizes, int n_in,
                              void* d_out, int out_size)
{
    const float* w   = (const float*)d_in[0];
    const float* r   = (const float*)d_in[1];
    const float* rwb = (const float*)d_in[2];
    const float* rrb = (const float*)d_in[3];
    const float* Wq  = (const float*)d_in[4];
    const float* Wkv = (const float*)d_in[5];
    const float* Wr  = (const float*)d_in[6];
    const float* Wo  = (const float*)d_in[7];
    float* out = (float*)d_out;

    __half *qh16, *kvh, *rk16, *bd, *avh, *w16, *r16, *wq16, *wkv16, *wr16, *wo16;
    cudaGetSymbolAddress((void**)&qh16,  g_qh16);
    cudaGetSymbolAddress((void**)&kvh,   g_kvh);
    cudaGetSymbolAddress((void**)&rk16,  g_rk16);
    cudaGetSymbolAddress((void**)&bd,    g_bd);
    cudaGetSymbolAddress((void**)&avh,   g_avh);
    cudaGetSymbolAddress((void**)&w16,   g_w16);
    cudaGetSymbolAddress((void**)&r16,   g_r16);
    cudaGetSymbolAddress((void**)&wq16,  g_wq16);
    cudaGetSymbolAddress((void**)&wkv16, g_wkv16);
    cudaGetSymbolAddress((void**)&wr16,  g_wr16);
    cudaGetSymbolAddress((void**)&wo16,  g_wo16);

    static cudaStream_t st1 = 0, st2 = 0;
    static cudaEvent_t ev0 = 0, evT = 0, evKV = 0, evR = 0, evZ = 0;
    if (!st1) {
        cudaStreamCreateWithFlags(&st1, cudaStreamNonBlocking);
        cudaStreamCreateWithFlags(&st2, cudaStreamNonBlocking);
        cudaEventCreateWithFlags(&ev0,  cudaEventDisableTiming);
        cudaEventCreateWithFlags(&evT,  cudaEventDisableTiming);
        cudaEventCreateWithFlags(&evKV, cudaEventDisableTiming);
        cudaEventCreateWithFlags(&evR,  cudaEventDisableTiming);
        cudaEventCreateWithFlags(&evZ,  cudaEventDisableTiming);
        cudaFuncSetAttribute(scores_bd_fp16,
                             cudaFuncAttributeMaxDynamicSharedMemorySize,
                             128 * 129 * 4);
        cudaFuncSetAttribute(attn_fused,
                             cudaFuncAttributeMaxDynamicSharedMemorySize,
                             4 * KHALF * 2);
    }
    const int score_smem = 128 * 129 * 4;
    const int fused_smem = 4 * KHALF * 2;   // 73728 B
    const size_t WTAIL = (size_t)QLEN * BSZ * DM;

    cudaEventRecord(ev0, 0);
    cudaStreamWaitEvent(st1, ev0, 0);
    cudaStreamWaitEvent(st2, ev0, 0);

    // stream 0: convert w TAIL (needed by Wq), then Wq chain
    {
        int n4 = (int)(WTAIL / 4);
        f2h_kernel<<<(n4 + 255) / 256, 256, 0, 0>>>(w + WTAIL, w16 + WTAIL, n4);
    }
    cudaEventRecord(evT, 0);
    {
        int n4 = DM * NHD / 4;
        f2h_kernel<<<(n4 + 255) / 256, 256, 0, 0>>>(Wq, wq16, n4);
    }
    gemm_fp16<__half><<<dim3(1024 / 128, 2048 / 128), 256, 0, 0>>>(
        w16 + WTAIL, wq16, qh16, 2048, 1024, 1024);

    // st1: convert w HEAD + Wkv, then Wkv projection
    {
        int n4 = (int)(WTAIL / 4);
        f2h_kernel<<<(n4 + 255) / 256, 256, 0, st1>>>(w, w16, n4);
        n4 = DM * 2 * NHD / 4;
        f2h_kernel<<<(n4 + 255) / 256, 256, 0, st1>>>(Wkv, wkv16, n4);
    }
    cudaStreamWaitEvent(st1, evT, 0);
    gemm_fp16<__half><<<dim3(2048 / 128, 4096 / 128), 256, 0, st1>>>(
        w16, wkv16, kvh, 4096, 2048, 1024);
    cudaEventRecord(evKV, st1);

    // st2: convert r/Wr/Wo, Wr projection, then zero_diag
    {
        int n4 = RLEN * DM / 4;
        f2h_kernel<<<(n4 + 255) / 256, 256, 0, st2>>>(r, r16, n4);
        n4 = DM * NHD / 4;
        f2h_kernel<<<(n4 + 255) / 256, 256, 0, st2>>>(Wr, wr16, n4);
        n4 = NHD * DM / 4;
        f2h_kernel<<<(n4 + 255) / 256, 256, 0, st2>>>(Wo, wo16, n4);
    }
    gemm_fp16<__half><<<dim3(1024 / 128, 2048 / 128), 256, 0, st2>>>(
        r16, wr16, rk16, 2048, 1024, 1024);
    cudaEventRecord(evR, st2);
    zero_diag<<<32, 1024, 0, st2>>>(bd);
    cudaEventRecord(evZ, st2);

    // stream 0: BD scores
    cudaStreamWaitEvent(0, evR, 0);
    scores_bd_fp16<<<dim3(RLEN / 128, QLEN / 128, 32), 256, score_smem, 0>>>(
        qh16, rk16, rrb, bd);

    // stream 0: fused attention
    cudaStreamWaitEvent(0, evKV, 0);
    cudaStreamWaitEvent(0, evZ, 0);
    attn_fused<<<dim3(QLEN / 128, BSZ * NH), 256, fused_smem, 0>>>(
        qh16, kvh, bd, rwb, avh);

    // output projection
    gemm_fp16<float><<<dim3(1024 / 128, 2048 / 128), 256, 0, 0>>>(
        avh, wo16, out, 2048, 1024, 1024);
}

// round 16
// speedup vs baseline: 1.0118x; 1.0118x over previous
#include <cuda_runtime.h>
#include <cuda_fp16.h>
#include <math.h>
#include <stdint.h>

#define QLEN 1024
#define KLEN 2048
#define RLEN 2048
#define BSZ  2
#define DM   1024
#define NH   16
#define DH   64
#define NHD  1024   // NH*DH

#define BDSTRIDE 2049
#define BDSZ     2098176   // per-(b,n) shifted-BD buffer

// scale folded with log2(e): exp(0.125*x) = exp2(SCL*x)
#define SCL 0.18033688f

// -------------------- scratch (device globals) ------------------------------
__device__ __half g_qh16[QLEN * BSZ * NHD];
__device__ __half g_kvh[KLEN * BSZ * 2 * NHD];
__device__ __half g_rk16[RLEN * NHD];
__device__ __half g_bd[(size_t)BSZ * NH * BDSZ];   // fp16, pre-scaled by SCL
__device__ __half g_avh[QLEN * BSZ * NHD];
__device__ __half g_w16[KLEN * BSZ * DM];
__device__ __half g_r16[RLEN * DM];
__device__ __half g_wq16[DM * NHD];
__device__ __half g_wkv16[DM * 2 * NHD];
__device__ __half g_wr16[DM * NHD];
__device__ __half g_wo16[NHD * DM];

// -------------------- helpers ------------------------------------------------
__device__ __forceinline__ uint32_t h2(float x, float y) {
    __half2 h = __floats2half2_rn(x, y);
    return *reinterpret_cast<uint32_t*>(&h);
}

__device__ __forceinline__ uint32_t ex2h2(uint32_t x) {
    uint32_t y;
    asm("ex2.approx.f16x2 %0, %1;" : "=r"(y) : "r"(x));
    return y;
}

__device__ __forceinline__ void mma16(float* d, const uint32_t* a, uint32_t b0, uint32_t b1) {
    asm volatile(
        "mma.sync.aligned.m16n8k16.row.col.f32.f16.f16.f32 "
        "{%0,%1,%2,%3},{%4,%5,%6,%7},{%8,%9},{%0,%1,%2,%3};\n"
        : "+f"(d[0]), "+f"(d[1]), "+f"(d[2]), "+f"(d[3])
        : "r"(a[0]), "r"(a[1]), "r"(a[2]), "r"(a[3]), "r"(b0), "r"(b1));
}

__device__ __forceinline__ void cpa16(uint32_t dst, const void* src) {
    asm volatile("cp.async.ca.shared.global [%0], [%1], 16;" :: "r"(dst), "l"(src));
}
__device__ __forceinline__ void cpa_commit() {
    asm volatile("cp.async.commit_group;");
}
template<int N> __device__ __forceinline__ void cpa_wait() {
    asm volatile("cp.async.wait_group %0;" :: "n"(N));
}

__device__ __forceinline__ void ldmx4t(uint32_t& r0, uint32_t& r1, uint32_t& r2, uint32_t& r3,
                                       uint32_t addr) {
    asm volatile("ldmatrix.sync.aligned.m8n8.x4.trans.shared.b16 {%0,%1,%2,%3}, [%4];"
                 : "=r"(r0), "=r"(r1), "=r"(r2), "=r"(r3) : "r"(addr));
}
__device__ __forceinline__ void ldmx4(uint32_t& r0, uint32_t& r1, uint32_t& r2, uint32_t& r3,
                                      uint32_t addr) {
    asm volatile("ldmatrix.sync.aligned.m8n8.x4.shared.b16 {%0,%1,%2,%3}, [%4];"
                 : "=r"(r0), "=r"(r1), "=r"(r2), "=r"(r3) : "r"(addr));
}

__device__ __forceinline__ void store_pair(float* p, float a, float b) {
    *(float2*)p = make_float2(a, b);
}
__device__ __forceinline__ void store_pair(__half* p, float a, float b) {
    *(__half2*)p = __floats2half2_rn(a, b);
}

// -------------------- fp32 -> fp16 convert ----------------------------------
__global__ void f2h_kernel(const float* __restrict__ in, __half* __restrict__ out, int n4) {
    int i = blockIdx.x * blockDim.x + threadIdx.x;
    if (i < n4) {
        float4 v = ((const float4*)in)[i];
        ((__half2*)out)[i * 2]     = __floats2half2_rn(v.x, v.y);
        ((__half2*)out)[i * 2 + 1] = __floats2half2_rn(v.z, v.w);
    }
}

// -------------------- fp16 GEMM (validated R13) ------------------------------
#define GS 3
#define AH (128 * 40)
#define BH (32 * 136)
#define STH (AH + BH)
template <typename OutT>
__global__ __launch_bounds__(256) void gemm_fp16(
    const __half* __restrict__ A, const __half* __restrict__ B,
    OutT* __restrict__ C, int M, int N, int K)
{
    __shared__ __half Sg[GS * STH];
    const uint32_t sbase = (uint32_t)__cvta_generic_to_shared(Sg);

    const int tid  = threadIdx.x;
    const int lane = tid & 31;
    const int warp = tid >> 5;
    const int row = lane >> 2;
    const int qd  = lane & 3;
    const int wm = (warp >> 2) * 64;
    const int wn = (warp & 3) * 32;
    const int row0 = blockIdx.y * 128, col0 = blockIdx.x * 128;

    float acc[4][4][4];
    #pragma unroll
    for (int i = 0; i < 4; i++)
        #pragma unroll
        for (int j = 0; j < 4; j++)
            #pragma unroll
            for (int r = 0; r < 4; r++) acc[i][j][r] = 0.0f;

    const int am = tid >> 1, ah = (tid & 1) * 16;
    const int bk = tid >> 3, bh = (tid & 7) * 16;
    const __half* aptr = A + (size_t)(row0 + am) * K + ah;
    const __half* bptr = B + (size_t)bk * N + col0 + bh;

    const int nsteps = K >> 5;
    const int a_r = ((lane >> 3) & 1) * 8 + (lane & 7);
    const int a_c = ((lane >> 4) & 1) * 8;

    #pragma unroll
    for (int s = 0; s < GS; s++) {
        if (s < nsteps) {
            uint32_t ab = sbase + (uint32_t)(s * STH + am * 40 + ah) * 2;
            cpa16(ab,      aptr + (s << 5));
            cpa16(ab + 16, aptr + (s << 5) + 8);
            uint32_t bb = sbase + (uint32_t)(s * STH + AH + bk * 136 + bh) * 2;
            cpa16(bb,      bptr + (size_t)(s << 5) * N);
            cpa16(bb + 16, bptr + (size_t)(s << 5) * N + 8);
        }
        cpa_commit();
    }

    int buf = 0;
    for (int t = 0; t < nsteps; t++) {
        cpa_wait<GS - 1>();
        __syncthreads();

        const uint32_t aoff = (uint32_t)(buf * STH);
        const uint32_t boff = (uint32_t)(buf * STH + AH);

        #pragma unroll
        for (int kk = 0; kk < 32; kk += 16) {
            uint32_t af[4][4];
            #pragma unroll
            for (int mt = 0; mt < 4; mt++) {
                uint32_t addr = sbase +
                    (aoff + (uint32_t)(wm + mt * 16 + a_r) * 40 + kk + a_c) * 2;
                ldmx4(af[mt][0], af[mt][1], af[mt][2], af[mt][3], addr);
            }
            #pragma unroll
            for (int ns = 0; ns < 2; ns++) {
                uint32_t r0, r1, r2, r3;
                uint32_t addr = sbase +
                    (boff + (kk + (lane & 15)) * 136 + wn + ns * 16 + (lane >> 4) * 8) * 2;
                ldmx4t(r0, r1, r2, r3, addr);
                #pragma unroll
                for (int mt = 0; mt < 4; mt++) {
                    mma16(acc[mt][ns * 2],     af[mt], r0, r1);
                    mma16(acc[mt][ns * 2 + 1], af[mt], r2, r3);
                }
            }
        }
        __syncthreads();

        const int tn = t + GS;
        if (tn < nsteps) {
            uint32_t ab = sbase + (uint32_t)(buf * STH + am * 40 + ah) * 2;
            cpa16(ab,      aptr + (tn << 5));
            cpa16(ab + 16, aptr + (tn << 5) + 8);
            uint32_t bb = sbase + (uint32_t)(buf * STH + AH + bk * 136 + bh) * 2;
            cpa16(bb,      bptr + (size_t)(tn << 5) * N);
            cpa16(bb + 16, bptr + (size_t)(tn << 5) * N + 8);
        }
        cpa_commit();
        buf = (buf + 1 == GS) ? 0 : buf + 1;
    }

    #pragma unroll
    for (int mt = 0; mt < 4; mt++)
        #pragma unroll
        for (int nt = 0; nt < 4; nt++) {
            int r = row0 + wm + mt * 16 + row;
            int c = col0 + wn + nt * 8 + 2 * qd;
            store_pair(&C[(size_t)r * N + c],       acc[mt][nt][0], acc[mt][nt][1]);
            store_pair(&C[(size_t)(r + 8) * N + c], acc[mt][nt][2], acc[mt][nt][3]);
        }
}

// -------------------- BD scores (fp16) -> shifted layout, SCL pre-scale -----
extern __shared__ uint32_t s_dyn[];
__global__ __launch_bounds__(256) void scores_bd_fp16(
    const __half* __restrict__ qh, const __half* __restrict__ rk,
    const float* __restrict__ bias, __half* __restrict__ out)
{
    __half (*Qs)[72] = (__half(*)[72])s_dyn;
    __half (*Ks)[72] = (__half(*)[72])(s_dyn + 128 * 36);

    const int bn = blockIdx.z;
    const int b = bn >> 4, n = bn & 15;
    const int j0 = blockIdx.x * 128, i0 = blockIdx.y * 128;
    const int tid  = threadIdx.x;
    const int lane = tid & 31;
    const int warp = tid >> 5;
    const int row = lane >> 2;
    const int qd  = lane & 3;
    const int wm = (warp >> 2) * 64;
    const int wn = (warp & 3) * 32;

    const int m = tid >> 1, half = (tid & 1) * 32;
    const __half* qrow = qh + (size_t)((i0 + m) * 2 + b) * NHD + n * DH + half;
    const __half* krow = rk + (size_t)(j0 + m) * NHD + n * DH + half;
    const float4* bias4 = (const float4*)(bias + n * DH + half);

    #pragma unroll
    for (int q = 0; q < 4; q++) {
        uint4 v = ((const uint4*)qrow)[q];
        float4 b0 = bias4[2 * q], b1 = bias4[2 * q + 1];
        float2 f0 = __half22float2(*reinterpret_cast<__half2*>(&v.x));
        float2 f1 = __half22float2(*reinterpret_cast<__half2*>(&v.y));
        float2 f2 = __half22float2(*reinterpret_cast<__half2*>(&v.z));
        float2 f3 = __half22float2(*reinterpret_cast<__half2*>(&v.w));
        int d = half + q * 8;
        *(uint2*)&Qs[m][d]     = make_uint2(h2(f0.x + b0.x, f0.y + b0.y),
                                            h2(f1.x + b0.z, f1.y + b0.w));
        *(uint2*)&Qs[m][d + 4] = make_uint2(h2(f2.x + b1.x, f2.y + b1.y),
                                            h2(f3.x + b1.z, f3.y + b1.w));
        *(uint4*)&Ks[m][d] = ((const uint4*)krow)[q];
    }
    __syncthreads();

    float acc[4][4][4];
    #pragma unroll
    for (int i = 0; i < 4; i++)
        #pragma unroll
        for (int j = 0; j < 4; j++)
            #pragma unroll
            for (int r = 0; r < 4; r++) acc[i][j][r] = 0.0f;

    #pragma unroll
    for (int g = 0; g < 4; g++) {
        uint32_t af[4][4];
        #pragma unroll
        for (int mt = 0; mt < 4; mt++) {
            int r = wm + mt * 16 + row;
            const __half* p0 = &Qs[r][g * 16 + 2 * qd];
            af[mt][0] = *(const uint32_t*)p0;
            af[mt][1] = *(const uint32_t*)(p0 + 8 * 72);
            af[mt][2] = *(const uint32_t*)(p0 + 8);
            af[mt][3] = *(const uint32_t*)(p0 + 8 * 72 + 8);
        }
        #pragma unroll
        for (int nt = 0; nt < 4; nt++) {
            int j = wn + nt * 8 + row;
            const __half* pk = &Ks[j][g * 16 + 2 * qd];
            uint32_t b0 = *(const uint32_t*)pk;
            uint32_t b1 = *(const uint32_t*)(pk + 8);
            #pragma unroll
            for (int mt = 0; mt < 4; mt++) mma16(acc[mt][nt], af[mt], b0, b1);
        }
    }

    __syncthreads();
    float (*St)[129] = (float(*)[129])s_dyn;
    #pragma unroll
    for (int mt = 0; mt < 4; mt++)
        #pragma unroll
        for (int nt = 0; nt < 4; nt++) {
            int r = wm + mt * 16 + row;
            int c = wn + nt * 8 + 2 * qd;
            St[r][c]     = acc[mt][nt][0] * SCL;
            St[r][c + 1] = acc[mt][nt][1] * SCL;
            St[r + 8][c]     = acc[mt][nt][2] * SCL;
            St[r + 8][c + 1] = acc[mt][nt][3] * SCL;
        }
    __syncthreads();

    __half* ob = out + (size_t)bn * BDSZ;
    #pragma unroll
    for (int rr = 0; rr < 16; rr++) {
        int r = warp * 16 + rr;
        size_t base = (size_t)(i0 + r) * BDSTRIDE + j0 + 1;
        #pragma unroll
        for (int mth = 0; mth < 4; mth++)
            ob[base + lane + 32 * mth] = __float2half_rn(St[r][lane + 32 * mth]);
    }
}

// zero the "dropped column" positions of the shifted buffer
__global__ void zero_diag(__half* __restrict__ buf) {
    int k = blockIdx.x * blockDim.x + threadIdx.x;
    int bn = k >> 10, kk = k & 1023;
    if (kk >= 1)
        buf[(size_t)bn * BDSZ + (size_t)kk * BDSTRIDE] = __float2half(0.0f);
}

// -------------------- fused attention: ex2.f16x2 softmax --------------------
#define KHALF  (128 * 72)
#define VBASEH (2 * KHALF)
__global__ __launch_bounds__(256, 2) void attn_fused(
    const __half* __restrict__ qh, const __half* __restrict__ kvh,
    const __half* __restrict__ bdbuf, const float* __restrict__ rwb,
    __half* __restrict__ av)
{
    extern __shared__ __half smh[];
    const uint32_t sbase = (uint32_t)__cvta_generic_to_shared(smh);

    const int bn = blockIdx.y;
    const int b = bn >> 4, n = bn & 15;
    const int i0 = blockIdx.x * 128;
    const int tid  = threadIdx.x;
    const int lane = tid & 31;
    const int warp = tid >> 5;
    const int row = lane >> 2;
    const int qd  = lane & 3;
    const int irow = i0 + warp * 16 + row;

    const int st_row = tid >> 1;
    const int st_h   = (tid & 1) * 32;

    const int k_r = ((lane >> 4) & 1) * 8 + (lane & 7);
    const int k_c = ((lane >> 3) & 1) * 8;

    uint32_t qf[4][4];
    {
        const __half* q0 = qh + (size_t)(irow * 2 + b) * NHD + n * DH;
        const __half* q1 = q0 + 16 * NHD;
        const float* bias = rwb + n * DH;
        #pragma unroll
        for (int g = 0; g < 4; g++) {
            int d0 = g * 16 + 2 * qd;
            float2 a0 = __half22float2(*(const __half2*)&q0[d0]);
            float2 a1 = __half22float2(*(const __half2*)&q1[d0]);
            float2 a2 = __half22float2(*(const __half2*)&q0[d0 + 8]);
            float2 a3 = __half22float2(*(const __half2*)&q1[d0 + 8]);
            qf[g][0] = h2((a0.x + bias[d0])   * SCL, (a0.y + bias[d0+1]) * SCL);
            qf[g][1] = h2((a1.x + bias[d0])   * SCL, (a1.y + bias[d0+1]) * SCL);
            qf[g][2] = h2((a2.x + bias[d0+8]) * SCL, (a2.y + bias[d0+9]) * SCL);
            qf[g][3] = h2((a3.x + bias[d0+8]) * SCL, (a3.y + bias[d0+9]) * SCL);
        }
    }

    float Ov[8][4];
    #pragma unroll
    for (int dt = 0; dt < 8; dt++)
        #pragma unroll
        for (int r = 0; r < 4; r++) Ov[dt][r] = 0.0f;
    float l0 = 0.0f, l1 = 0.0f;

    const __half* bdp = bdbuf + (size_t)bn * BDSZ + 1024;

    #pragma unroll
    for (int i = 0; i < 4; i++)
        cpa16(sbase + (uint32_t)(st_row * 72 + st_h + i * 8) * 2,
              kvh + ((size_t)st_row * 2 + b) * (2 * NHD) + n * DH + st_h + i * 8);
    cpa_commit();
    #pragma unroll
    for (int i = 0; i < 4; i++)
        cpa16(sbase + (uint32_t)(VBASEH + st_row * 72 + st_h + i * 8) * 2,
              kvh + ((size_t)st_row * 2 + b) * (2 * NHD) + NHD + n * DH + st_h + i * 8);
    cpa_commit();

    for (int t = 0; t < 16; t++) {
        const int j0 = t * 128;
        const int kb = t & 1;

        cpa_wait<1>();
        __syncthreads();

        if (t + 1 < 16) {
            const int kboff = (kb ^ 1) * KHALF;
            #pragma unroll
            for (int i = 0; i < 4; i++)
                cpa16(sbase + (uint32_t)(kboff + st_row * 72 + st_h + i * 8) * 2,
                      kvh + ((size_t)(j0 + 128 + st_row) * 2 + b) * (2 * NHD) + n * DH + st_h + i * 8);
        }
        cpa_commit();

        #pragma unroll
        for (int ch = 0; ch < 2; ch++) {
            const int jl = ch * 64;

            // init s with SCL-pre-scaled fp16 shifted-BD
            float s[8][4];
            #pragma unroll
            for (int nt = 0; nt < 8; nt++) {
                int jc = j0 + jl + nt * 8 + 2 * qd;
                uint32_t u0 = __ldcs((const uint32_t*)(bdp + (size_t)irow * KLEN + jc));
                uint32_t u1 = __ldcs((const uint32_t*)(bdp + (size_t)(irow + 8) * KLEN + jc));
                float2 f0 = __half22float2(*reinterpret_cast<__half2*>(&u0));
                float2 f1 = __half22float2(*reinterpret_cast<__half2*>(&u1));
                s[nt][0] = f0.x; s[nt][1] = f0.y;
                s[nt][2] = f1.x; s[nt][3] = f1.y;
            }

            // S += Q~ . K^T
            #pragma unroll
            for (int g = 0; g < 4; g++) {
                #pragma unroll
                for (int ntp = 0; ntp < 4; ntp++) {
                    int j = jl + ntp * 16 + k_r;
                    uint32_t addr = sbase +
                        (uint32_t)(kb * KHALF + j * 72 + g * 16 + k_c) * 2;
                    uint32_t r0, r1, r2, r3;
                    ldmx4(r0, r1, r2, r3, addr);
                    mma16(s[2 * ntp],     qf[g], r0, r1);
                    mma16(s[2 * ntp + 1], qf[g], r2, r3);
                }
            }

            // P = exp2(s) in fp16x2 (half the MUFU ops); fp32 row-sum
            uint32_t ph[8][2];
            {
                float ps0 = 0.0f, ps1 = 0.0f;
                #pragma unroll
                for (int nt = 0; nt < 8; nt++) {
                    ph[nt][0] = ex2h2(h2(s[nt][0], s[nt][1]));
                    ph[nt][1] = ex2h2(h2(s[nt][2], s[nt][3]));
                    float2 f0 = __half22float2(*reinterpret_cast<__half2*>(&ph[nt][0]));
                    float2 f1 = __half22float2(*reinterpret_cast<__half2*>(&ph[nt][1]));
                    ps0 += f0.x + f0.y;
                    ps1 += f1.x + f1.y;
                }
                l0 += ps0;
                l1 += ps1;
            }

            if (ch == 0) {
                cpa_wait<1>();
                __syncthreads();
            }

            // O += P . V  (A-frags are the ex2 outputs directly)
            #pragma unroll
            for (int g = 0; g < 4; g++) {
                uint32_t a[4];
                a[0] = ph[2*g][0];
                a[1] = ph[2*g][1];
                a[2] = ph[2*g+1][0];
                a[3] = ph[2*g+1][1];
                #pragma unroll
                for (int dp = 0; dp < 4; dp++) {
                    int jrow = jl + g * 16 + (lane & 15);
                    int dcol = (dp * 2 + (lane >> 4)) * 8;
                    uint32_t addr = sbase + (uint32_t)(VBASEH + jrow * 72 + dcol) * 2;
                    uint32_t r0, r1, r2, r3;
                    ldmx4t(r0, r1, r2, r3, addr);
                    mma16(Ov[dp * 2],     a, r0, r1);
                    mma16(Ov[dp * 2 + 1], a, r2, r3);
                }
            }
        }

        __syncthreads();
        if (t + 1 < 16) {
            #pragma unroll
            for (int i = 0; i < 4; i++)
                cpa16(sbase + (uint32_t)(VBASEH + st_row * 72 + st_h + i * 8) * 2,
                      kvh + ((size_t)(j0 + 128 + st_row) * 2 + b) * (2 * NHD) + NHD + n * DH + st_h + i * 8);
        }
        cpa_commit();
    }

    cpa_wait<0>();

    {
        float ll0 = l0, ll1 = l1;
        ll0 += __shfl_xor_sync(0xffffffffu, ll0, 1);
        ll0 += __shfl_xor_sync(0xffffffffu, ll0, 2);
        ll1 += __shfl_xor_sync(0xffffffffu, ll1, 1);
        ll1 += __shfl_xor_sync(0xffffffffu, ll1, 2);
        float inv0 = 1.0f / ll0, inv1 = 1.0f / ll1;
        #pragma unroll
        for (int dt = 0; dt < 8; dt++) {
            int d = n * DH + dt * 8 + 2 * qd;
            *(__half2*)&av[(size_t)(irow * 2 + b) * NHD + d] =
                __floats2half2_rn(Ov[dt][0] * inv0, Ov[dt][1] * inv0);
            *(__half2*)&av[(size_t)((irow + 8) * 2 + b) * NHD + d] =
                __floats2half2_rn(Ov[dt][2] * inv1, Ov[dt][3] * inv1);
        }
    }
}

// ---------------------------------------------------------------------------
extern "C" void kernel_launch(void* const* d_in, const int* in_sizes, int n_in,
                              void* d_out, int out_size)
{
    const float* w   = (const float*)d_in[0];
    const float* r   = (const float*)d_in[1];
    const float* rwb = (const float*)d_in[2];
    const float* rrb = (const float*)d_in[3];
    const float* Wq  = (const float*)d_in[4];
    const float* Wkv = (const float*)d_in[5];
    const float* Wr  = (const float*)d_in[6];
    const float* Wo  = (const float*)d_in[7];
    float* out = (float*)d_out;

    __half *qh16, *kvh, *rk16, *bd, *avh, *w16, *r16, *wq16, *wkv16, *wr16, *wo16;
    cudaGetSymbolAddress((void**)&qh16,  g_qh16);
    cudaGetSymbolAddress((void**)&kvh,   g_kvh);
    cudaGetSymbolAddress((void**)&rk16,  g_rk16);
    cudaGetSymbolAddress((void**)&bd,    g_bd);
    cudaGetSymbolAddress((void**)&avh,   g_avh);
    cudaGetSymbolAddress((void**)&w16,   g_w16);
    cudaGetSymbolAddress((void**)&r16,   g_r16);
    cudaGetSymbolAddress((void**)&wq16,  g_wq16);
    cudaGetSymbolAddress((void**)&wkv16, g_wkv16);
    cudaGetSymbolAddress((void**)&wr16,  g_wr16);
    cudaGetSymbolAddress((void**)&wo16,  g_wo16);

    static cudaStream_t st1 = 0, st2 = 0;
    static cudaEvent_t ev0 = 0, evT = 0, evKV = 0, evR = 0, evZ = 0;
    if (!st1) {
        cudaStreamCreateWithFlags(&st1, cudaStreamNonBlocking);
        cudaStreamCreateWithFlags(&st2, cudaStreamNonBlocking);
        cudaEventCreateWithFlags(&ev0,  cudaEventDisableTiming);
        cudaEventCreateWithFlags(&evT,  cudaEventDisableTiming);
        cudaEventCreateWithFlags(&evKV, cudaEventDisableTiming);
        cudaEventCreateWithFlags(&evR,  cudaEventDisableTiming);
        cudaEventCreateWithFlags(&evZ,  cudaEventDisableTiming);
        cudaFuncSetAttribute(scores_bd_fp16,
                             cudaFuncAttributeMaxDynamicSharedMemorySize,
                             128 * 129 * 4);
        cudaFuncSetAttribute(attn_fused,
                             cudaFuncAttributeMaxDynamicSharedMemorySize,
                             (VBASEH + KHALF) * 2);
    }
    const int score_smem = 128 * 129 * 4;
    const int fused_smem = (VBASEH + KHALF) * 2;
    const size_t WTAIL = (size_t)QLEN * BSZ * DM;

    cudaEventRecord(ev0, 0);
    cudaStreamWaitEvent(st1, ev0, 0);
    cudaStreamWaitEvent(st2, ev0, 0);

    // stream 0: convert w TAIL (needed by Wq), then Wq chain
    {
        int n4 = (int)(WTAIL / 4);
        f2h_kernel<<<(n4 + 255) / 256, 256, 0, 0>>>(w + WTAIL, w16 + WTAIL, n4);
    }
    cudaEventRecord(evT, 0);
    {
        int n4 = DM * NHD / 4;
        f2h_kernel<<<(n4 + 255) / 256, 256, 0, 0>>>(Wq, wq16, n4);
    }
    gemm_fp16<__half><<<dim3(1024 / 128, 2048 / 128), 256, 0, 0>>>(
        w16 + WTAIL, wq16, qh16, 2048, 1024, 1024);

    // st1: convert w HEAD + Wkv, then Wkv projection
    {
        int n4 = (int)(WTAIL / 4);
        f2h_kernel<<<(n4 + 255) / 256, 256, 0, st1>>>(w, w16, n4);
        n4 = DM * 2 * NHD / 4;
        f2h_kernel<<<(n4 + 255) / 256, 256, 0, st1>>>(Wkv, wkv16, n4);
    }
    cudaStreamWaitEvent(st1, evT, 0);
    gemm_fp16<__half><<<dim3(2048 / 128, 4096 / 128), 256, 0, st1>>>(
        w16, wkv16, kvh, 4096, 2048, 1024);
    cudaEventRecord(evKV, st1);

    // st2: convert r/Wr/Wo, Wr projection, then zero_diag
    {
        int n4 = RLEN * DM / 4;
        f2h_kernel<<<(n4 + 255) / 256, 256, 0, st2>>>(r, r16, n4);
        n4 = DM * NHD / 4;
        f2h_kernel<<<(n4 + 255) / 256, 256, 0, st2>>>(Wr, wr16, n4);
        n4 = NHD * DM / 4;
        f2h_kernel<<<(n4 + 255) / 256, 256, 0, st2>>>(Wo, wo16, n4);
    }
    gemm_fp16<__half><<<dim3(1024 / 128, 2048 / 128), 256, 0, st2>>>(
        r16, wr16, rk16, 2048, 1024, 1024);
    cudaEventRecord(evR, st2);
    zero_diag<<<32, 1024, 0, st2>>>(bd);
    cudaEventRecord(evZ, st2);

    // stream 0: BD scores
    cudaStreamWaitEvent(0, evR, 0);
    scores_bd_fp16<<<dim3(RLEN / 128, QLEN / 128, 32), 256, score_smem, 0>>>(
        qh16, rk16, rrb, bd);

    // stream 0: fused attention
    cudaStreamWaitEvent(0, evKV, 0);
    cudaStreamWaitEvent(0, evZ, 0);
    attn_fused<<<dim3(QLEN / 128, BSZ * NH), 256, fused_smem, 0>>>(
        qh16, kvh, bd, rwb, avh);

    // output projection
    gemm_fp16<float><<<dim3(1024 / 128, 2048 / 128), 256, 0, 0>>>(
        avh, wo16, out, 2048, 1024, 1024);
}